// round 5
// baseline (speedup 1.0000x reference)
#include <cuda_runtime.h>
#include <math.h>
#include <stdint.h>

// ---- problem shape ----
#define BATCH 4
#define SEQL  1024
#define DM    1024
#define NH    16
#define HD    64
#define FF    4096
#define NE    8
#define TOPK  2
#define NTOK  (BATCH*SEQL)          // 4096 tokens
#define NSLOT 9216                  // 4096*2 + worst-case 128-align padding -> 9208 <= 9216

// GEMM tiling (tensor-core kernel)
#define BM 128
#define BN 64
#define BK 16

// ---- scratch (device globals; no runtime allocation allowed) ----
__device__ float g_nx  [(size_t)NTOK*DM];
__device__ float g_qkv [(size_t)NTOK*3*DM];
__device__ float g_attn[(size_t)NTOK*DM];
__device__ float g_x1  [(size_t)NTOK*DM];
__device__ float g_nx2 [(size_t)NTOK*DM];
__device__ int   g_top_idx[NTOK*TOPK];
__device__ float g_top_w  [NTOK*TOPK];
__device__ int   g_cnt [NE];
__device__ int   g_off [NE+1];
__device__ int   g_fill[NE];
__device__ int   g_slot2tok[NSLOT];
__device__ int   g_slot_expert[NSLOT];
__device__ int   g_tok2slot[NTOK*TOPK];
__device__ float g_h[(size_t)NSLOT*FF];
__device__ float g_y[(size_t)NSLOT*DM];

// ---------------- helpers ----------------
__device__ __forceinline__ uint32_t f2tf(float x) {
    uint32_t r;
    asm("cvt.rna.tf32.f32 %0, %1;" : "=r"(r) : "f"(x));
    return r;
}
// split x into tf32 hi + tf32(lo); both stored as fp32 bit patterns
__device__ __forceinline__ void split_tf32(float x, float& hi, float& lo) {
    uint32_t h = f2tf(x);
    hi = __uint_as_float(h);
    lo = __uint_as_float(f2tf(x - hi));
}
__device__ __forceinline__ void mma_tf32(float* c, const uint32_t* a, const uint32_t* b) {
    asm volatile("mma.sync.aligned.m16n8k8.row.col.f32.tf32.tf32.f32 "
                 "{%0,%1,%2,%3}, {%4,%5,%6,%7}, {%8,%9}, {%0,%1,%2,%3};"
                 : "+f"(c[0]), "+f"(c[1]), "+f"(c[2]), "+f"(c[3])
                 : "r"(a[0]), "r"(a[1]), "r"(a[2]), "r"(a[3]), "r"(b[0]), "r"(b[1]));
}

// ---------------- LayerNorm ----------------
__device__ __forceinline__ void ln_body(const float* __restrict__ x, const float* __restrict__ w,
                                        const float* __restrict__ b, float* __restrict__ out) {
    int t = blockIdx.x;
    const float* row = x + (size_t)t * DM;
    float s = 0.f, s2 = 0.f;
    for (int i = threadIdx.x; i < DM; i += blockDim.x) {
        float v = row[i]; s += v; s2 += v * v;
    }
    __shared__ float sh[64];
    for (int o = 16; o > 0; o >>= 1) {
        s  += __shfl_down_sync(0xffffffffu, s,  o);
        s2 += __shfl_down_sync(0xffffffffu, s2, o);
    }
    int wid = threadIdx.x >> 5, lane = threadIdx.x & 31;
    if (lane == 0) { sh[wid] = s; sh[wid + 32] = s2; }
    __syncthreads();
    if (threadIdx.x == 0) {
        float a = 0.f, c = 0.f;
        int nw = blockDim.x >> 5;
        for (int i = 0; i < nw; i++) { a += sh[i]; c += sh[i + 32]; }
        float mu  = a / DM;
        float var = c / DM - mu * mu;
        sh[0] = mu; sh[1] = rsqrtf(var + 1e-5f);
    }
    __syncthreads();
    float mu = sh[0], rs = sh[1];
    for (int i = threadIdx.x; i < DM; i += blockDim.x)
        out[(size_t)t * DM + i] = (row[i] - mu) * rs * w[i] + b[i];
}

__global__ void __launch_bounds__(256) ln1_kernel(const float* __restrict__ x,
                                                  const float* __restrict__ w,
                                                  const float* __restrict__ b) {
    ln_body(x, w, b, g_nx);
}
__global__ void __launch_bounds__(256) ln2_kernel(const float* __restrict__ w,
                                                  const float* __restrict__ b) {
    ln_body(g_x1, w, b, g_nx2);
}

// ============ tensor-core GEMM (tf32x3, hi/lo pre-split in smem) ============
template<bool GROUPED, bool ROWMAP, bool TRANSB, bool ACT, bool RESID>
__device__ __forceinline__ void mma_gemm_body(
    const float* __restrict__ A, int lda,
    const float* __restrict__ Wbase, size_t wstride,
    const float* __restrict__ biasbase, int bstride,
    const float* __restrict__ resid,
    float* __restrict__ C, int N, int K)
{
    __shared__ float As_hi[BK][BM + 8], As_lo[BK][BM + 8];
    __shared__ float Bs_hi[BK][BN + 8], Bs_lo[BK][BN + 8];

    int m0 = blockIdx.y * BM, n0 = blockIdx.x * BN;
    const float* Bm; const float* bias;
    if (GROUPED) {
        if (m0 >= g_off[NE]) return;
        int e = g_slot_expert[m0];
        Bm   = Wbase   + (size_t)e * wstride;
        bias = biasbase + (size_t)e * bstride;
    } else {
        Bm = Wbase; bias = biasbase;
    }

    int tid  = threadIdx.x;
    int lane = tid & 31, warp = tid >> 5;
    int wm = warp & 3, wn = warp >> 2;       // 4 x 2 warp grid, warp tile 32x32
    int g  = lane >> 2, tg = lane & 3;

    float c[2][4][4];
#pragma unroll
    for (int mt = 0; mt < 2; mt++)
#pragma unroll
        for (int nt = 0; nt < 4; nt++)
#pragma unroll
            for (int i = 0; i < 4; i++) c[mt][nt][i] = 0.f;

    // staging indices
    int am[2], kqa[2], arow[2];
#pragma unroll
    for (int s = 0; s < 2; s++) {
        int idx = s * 256 + tid;
        am[s]  = idx >> 2;
        kqa[s] = idx & 3;
        int r = m0 + am[s];
        arow[s] = ROWMAP ? g_slot2tok[r] : r;
    }
    int kb = tid >> 4, nq = tid & 15;      // NN
    int nb = tid >> 2, kqb = tid & 3;      // NT

    float4 ra[2], rb;

    // prologue load (k0 = 0)
#pragma unroll
    for (int s = 0; s < 2; s++) {
        if (!ROWMAP || arow[s] >= 0)
            ra[s] = *(const float4*)&A[(size_t)arow[s] * lda + kqa[s] * 4];
        else
            ra[s] = make_float4(0.f, 0.f, 0.f, 0.f);
    }
    if (TRANSB) rb = *(const float4*)&Bm[(size_t)(n0 + nb) * K + kqb * 4];
    else        rb = *(const float4*)&Bm[(size_t)kb * N + n0 + nq * 4];

    for (int k0 = 0; k0 < K; k0 += BK) {
        __syncthreads();
        // commit staged regs to smem as hi/lo planes
#pragma unroll
        for (int s = 0; s < 2; s++) {
            float h, l;
            split_tf32(ra[s].x, h, l); As_hi[kqa[s]*4+0][am[s]] = h; As_lo[kqa[s]*4+0][am[s]] = l;
            split_tf32(ra[s].y, h, l); As_hi[kqa[s]*4+1][am[s]] = h; As_lo[kqa[s]*4+1][am[s]] = l;
            split_tf32(ra[s].z, h, l); As_hi[kqa[s]*4+2][am[s]] = h; As_lo[kqa[s]*4+2][am[s]] = l;
            split_tf32(ra[s].w, h, l); As_hi[kqa[s]*4+3][am[s]] = h; As_lo[kqa[s]*4+3][am[s]] = l;
        }
        {
            float h, l;
            if (TRANSB) {
                split_tf32(rb.x, h, l); Bs_hi[kqb*4+0][nb] = h; Bs_lo[kqb*4+0][nb] = l;
                split_tf32(rb.y, h, l); Bs_hi[kqb*4+1][nb] = h; Bs_lo[kqb*4+1][nb] = l;
                split_tf32(rb.z, h, l); Bs_hi[kqb*4+2][nb] = h; Bs_lo[kqb*4+2][nb] = l;
                split_tf32(rb.w, h, l); Bs_hi[kqb*4+3][nb] = h; Bs_lo[kqb*4+3][nb] = l;
            } else {
                split_tf32(rb.x, h, l); Bs_hi[kb][nq*4+0] = h; Bs_lo[kb][nq*4+0] = l;
                split_tf32(rb.y, h, l); Bs_hi[kb][nq*4+1] = h; Bs_lo[kb][nq*4+1] = l;
                split_tf32(rb.z, h, l); Bs_hi[kb][nq*4+2] = h; Bs_lo[kb][nq*4+2] = l;
                split_tf32(rb.w, h, l); Bs_hi[kb][nq*4+3] = h; Bs_lo[kb][nq*4+3] = l;
            }
        }
        __syncthreads();

        // prefetch next K-slab
        int kn = k0 + BK;
        if (kn < K) {
#pragma unroll
            for (int s = 0; s < 2; s++) {
                if (!ROWMAP || arow[s] >= 0)
                    ra[s] = *(const float4*)&A[(size_t)arow[s] * lda + kn + kqa[s] * 4];
                else
                    ra[s] = make_float4(0.f, 0.f, 0.f, 0.f);
            }
            if (TRANSB) rb = *(const float4*)&Bm[(size_t)(n0 + nb) * K + kn + kqb * 4];
            else        rb = *(const float4*)&Bm[(size_t)(kn + kb) * N + n0 + nq * 4];
        }

        // compute: 2 k-steps of 8 — pure LDS + MMA
#pragma unroll
        for (int ks = 0; ks < 2; ks++) {
            int k8 = ks * 8;
            uint32_t ahi[2][4], alo[2][4];
#pragma unroll
            for (int mt = 0; mt < 2; mt++) {
                int mb = wm * 32 + mt * 16;
                ahi[mt][0] = __float_as_uint(As_hi[k8 + tg][mb + g]);
                ahi[mt][1] = __float_as_uint(As_hi[k8 + tg][mb + g + 8]);
                ahi[mt][2] = __float_as_uint(As_hi[k8 + tg + 4][mb + g]);
                ahi[mt][3] = __float_as_uint(As_hi[k8 + tg + 4][mb + g + 8]);
                alo[mt][0] = __float_as_uint(As_lo[k8 + tg][mb + g]);
                alo[mt][1] = __float_as_uint(As_lo[k8 + tg][mb + g + 8]);
                alo[mt][2] = __float_as_uint(As_lo[k8 + tg + 4][mb + g]);
                alo[mt][3] = __float_as_uint(As_lo[k8 + tg + 4][mb + g + 8]);
            }
            uint32_t bhi[4][2], blo[4][2];
#pragma unroll
            for (int nt = 0; nt < 4; nt++) {
                int nbase = wn * 32 + nt * 8 + g;
                bhi[nt][0] = __float_as_uint(Bs_hi[k8 + tg][nbase]);
                bhi[nt][1] = __float_as_uint(Bs_hi[k8 + tg + 4][nbase]);
                blo[nt][0] = __float_as_uint(Bs_lo[k8 + tg][nbase]);
                blo[nt][1] = __float_as_uint(Bs_lo[k8 + tg + 4][nbase]);
            }
#pragma unroll
            for (int mt = 0; mt < 2; mt++)
#pragma unroll
                for (int nt = 0; nt < 4; nt++) {
                    mma_tf32(c[mt][nt], alo[mt], bhi[nt]);
                    mma_tf32(c[mt][nt], ahi[mt], blo[nt]);
                    mma_tf32(c[mt][nt], ahi[mt], bhi[nt]);
                }
        }
    }

    // epilogue
#pragma unroll
    for (int mt = 0; mt < 2; mt++) {
        int r0 = m0 + wm * 32 + mt * 16 + g;
#pragma unroll
        for (int nt = 0; nt < 4; nt++) {
            int cc = n0 + wn * 32 + nt * 8 + tg * 2;
            float b0 = bias[cc], b1 = bias[cc + 1];
#pragma unroll
            for (int half = 0; half < 2; half++) {
                int r = r0 + half * 8;
                float v0 = c[mt][nt][half * 2 + 0] + b0;
                float v1 = c[mt][nt][half * 2 + 1] + b1;
                if (ACT) {
                    v0 = 0.5f * v0 * (1.0f + erff(v0 * 0.70710678118654752f));
                    v1 = 0.5f * v1 * (1.0f + erff(v1 * 0.70710678118654752f));
                }
                if (RESID) {
                    v0 += resid[(size_t)r * N + cc];
                    v1 += resid[(size_t)r * N + cc + 1];
                }
                C[(size_t)r * N + cc]     = v0;
                C[(size_t)r * N + cc + 1] = v1;
            }
        }
    }
}

__global__ void __launch_bounds__(256) gemm_qkv(const float* __restrict__ Wqkv,
                                                const float* __restrict__ bqkv) {
    mma_gemm_body<false, false, false, false, false>(g_nx, DM, Wqkv, 0, bqkv, 0, nullptr,
                                                     g_qkv, 3 * DM, DM);
}
__global__ void __launch_bounds__(256) gemm_wo(const float* __restrict__ Wo,
                                               const float* __restrict__ bo,
                                               const float* __restrict__ x) {
    mma_gemm_body<false, false, false, false, true>(g_attn, DM, Wo, 0, bo, 0, x,
                                                    g_x1, DM, DM);
}
__global__ void __launch_bounds__(256) moe_fc1(const float* __restrict__ fc1_w,
                                               const float* __restrict__ fc1_b) {
    mma_gemm_body<true, true, true, true, false>(g_nx2, DM, fc1_w, (size_t)FF * DM,
                                                 fc1_b, FF, nullptr, g_h, FF, DM);
}
__global__ void __launch_bounds__(256) moe_fc2(const float* __restrict__ fc2_w,
                                               const float* __restrict__ fc2_b) {
    mma_gemm_body<true, false, true, false, false>(g_h, FF, fc2_w, (size_t)DM * FF,
                                                   fc2_b, DM, nullptr, g_y, DM, FF);
}

// ============ tensor-core flash attention: 64q x 64kk per block, tf32x3 ============
// XOR swizzle: element (row, col) stored at [row][col ^ ((row&7)<<3)]
#define SWZ(col, row) ((col) ^ (((row) & 7) << 3))

__global__ void __launch_bounds__(256) attn_mma_kernel() {
    __shared__ float Qs[64][64];   // Q^T: [d][q]
    __shared__ float KP[64][64];   // K^T: [d][kk]; later scratch + P^T: [kk][q]
    __shared__ float Vs[64][64];   // V:   [kk][d]
    float* scratch = &KP[0][0];    // 128 floats, used while K is dead

    const float* __restrict__ qkv = g_qkv;
    int qt = blockIdx.x, h = blockIdx.y, b = blockIdx.z;
    int tid = threadIdx.x, lane = tid & 31, warp = tid >> 5;
    int wm = warp & 3, wn = warp >> 2;   // warp tile: rows wm*16+{0..15}, cols wn*32+{0..31}
    int g = lane >> 2, tg = lane & 3;
    int row0 = wm * 16 + g, row1 = row0 + 8;

    // load Q^T with swizzle
#pragma unroll
    for (int r = 0; r < 4; r++) {
        int idx = r * 256 + tid;
        int q = idx >> 4, d0 = (idx & 15) * 4;
        float4 v = *(const float4*)&qkv[((size_t)(b * SEQL + qt * 64 + q)) * (3 * DM) + h * HD + d0];
        Qs[d0 + 0][SWZ(q, d0 + 0)] = v.x;
        Qs[d0 + 1][SWZ(q, d0 + 1)] = v.y;
        Qs[d0 + 2][SWZ(q, d0 + 2)] = v.z;
        Qs[d0 + 3][SWZ(q, d0 + 3)] = v.w;
    }

    float m2[2] = {-1e30f, -1e30f}, l2[2] = {0.f, 0.f};
    float o[4][4];
#pragma unroll
    for (int nt = 0; nt < 4; nt++)
#pragma unroll
        for (int i = 0; i < 4; i++) o[nt][i] = 0.f;

    for (int kt = 0; kt <= qt; kt++) {
        __syncthreads();  // previous PV reads (and Q stores on iter 0) complete
        // load K^T and V with swizzle
#pragma unroll
        for (int r = 0; r < 4; r++) {
            int idx = r * 256 + tid;
            int kk = idx >> 4, d0 = (idx & 15) * 4;
            size_t base = ((size_t)(b * SEQL + kt * 64 + kk)) * (3 * DM) + h * HD + d0;
            float4 kv = *(const float4*)&qkv[base + DM];
            KP[d0 + 0][SWZ(kk, d0 + 0)] = kv.x;
            KP[d0 + 1][SWZ(kk, d0 + 1)] = kv.y;
            KP[d0 + 2][SWZ(kk, d0 + 2)] = kv.z;
            KP[d0 + 3][SWZ(kk, d0 + 3)] = kv.w;
            float4 vv = *(const float4*)&qkv[base + 2 * DM];
            *(float4*)&Vs[kk][SWZ(d0, kk)] = vv;   // d0..d0+3 stay contiguous under swizzle
        }
        __syncthreads();

        // ---- S = Q K^T (tf32x3) ----
        float s[4][4];
#pragma unroll
        for (int nt = 0; nt < 4; nt++)
#pragma unroll
            for (int i = 0; i < 4; i++) s[nt][i] = 0.f;
#pragma unroll
        for (int k8 = 0; k8 < 64; k8 += 8) {
            uint32_t ahi[4], alo[4];
            {
                float x0 = Qs[k8 + tg][SWZ(row0, k8 + tg)];
                float x1 = Qs[k8 + tg][SWZ(row1, k8 + tg)];
                float x2 = Qs[k8 + tg + 4][SWZ(row0, k8 + tg + 4)];
                float x3 = Qs[k8 + tg + 4][SWZ(row1, k8 + tg + 4)];
                ahi[0] = f2tf(x0); alo[0] = f2tf(x0 - __uint_as_float(ahi[0]));
                ahi[1] = f2tf(x1); alo[1] = f2tf(x1 - __uint_as_float(ahi[1]));
                ahi[2] = f2tf(x2); alo[2] = f2tf(x2 - __uint_as_float(ahi[2]));
                ahi[3] = f2tf(x3); alo[3] = f2tf(x3 - __uint_as_float(ahi[3]));
            }
#pragma unroll
            for (int nt = 0; nt < 4; nt++) {
                int n = wn * 32 + nt * 8 + g;
                float b0f = KP[k8 + tg][SWZ(n, k8 + tg)];
                float b1f = KP[k8 + tg + 4][SWZ(n, k8 + tg + 4)];
                uint32_t bhi[2], blo[2];
                bhi[0] = f2tf(b0f); blo[0] = f2tf(b0f - __uint_as_float(bhi[0]));
                bhi[1] = f2tf(b1f); blo[1] = f2tf(b1f - __uint_as_float(bhi[1]));
                mma_tf32(s[nt], alo, bhi);
                mma_tf32(s[nt], ahi, blo);
                mma_tf32(s[nt], ahi, bhi);
            }
        }

        // ---- scale + causal mask ----
        bool diag = (kt == qt);
#pragma unroll
        for (int nt = 0; nt < 4; nt++) {
            int col = wn * 32 + nt * 8 + tg * 2;
#pragma unroll
            for (int i = 0; i < 4; i++) {
                float sv = s[nt][i] * 0.125f;
                int cc = col + (i & 1);
                int rr = (i < 2) ? row0 : row1;
                if (diag && cc > rr) sv = -1e30f;
                s[nt][i] = sv;
            }
        }
        // partial row max (this warp's 32 cols)
        float pm0 = -1e30f, pm1 = -1e30f;
#pragma unroll
        for (int nt = 0; nt < 4; nt++) {
            pm0 = fmaxf(pm0, fmaxf(s[nt][0], s[nt][1]));
            pm1 = fmaxf(pm1, fmaxf(s[nt][2], s[nt][3]));
        }
        pm0 = fmaxf(pm0, __shfl_xor_sync(0xffffffffu, pm0, 1));
        pm0 = fmaxf(pm0, __shfl_xor_sync(0xffffffffu, pm0, 2));
        pm1 = fmaxf(pm1, __shfl_xor_sync(0xffffffffu, pm1, 1));
        pm1 = fmaxf(pm1, __shfl_xor_sync(0xffffffffu, pm1, 2));

        __syncthreads();   // K reads finished -> scratch (KP rows 0-1) writable
        scratch[wn * 64 + row0] = pm0;   // 4 tg-lanes write identical value
        scratch[wn * 64 + row1] = pm1;
        __syncthreads();
        float nm0 = fmaxf(m2[0], fmaxf(scratch[row0], scratch[64 + row0]));
        float nm1 = fmaxf(m2[1], fmaxf(scratch[row1], scratch[64 + row1]));

        float ps0 = 0.f, ps1 = 0.f;
#pragma unroll
        for (int nt = 0; nt < 4; nt++) {
            s[nt][0] = __expf(s[nt][0] - nm0); ps0 += s[nt][0];
            s[nt][1] = __expf(s[nt][1] - nm0); ps0 += s[nt][1];
            s[nt][2] = __expf(s[nt][2] - nm1); ps1 += s[nt][2];
            s[nt][3] = __expf(s[nt][3] - nm1); ps1 += s[nt][3];
        }
        ps0 += __shfl_xor_sync(0xffffffffu, ps0, 1);
        ps0 += __shfl_xor_sync(0xffffffffu, ps0, 2);
        ps1 += __shfl_xor_sync(0xffffffffu, ps1, 1);
        ps1 += __shfl_xor_sync(0xffffffffu, ps1, 2);

        __syncthreads();   // all max reads done before overwriting scratch
        scratch[wn * 64 + row0] = ps0;
        scratch[wn * 64 + row1] = ps1;
        __syncthreads();
        float rs0 = scratch[row0] + scratch[64 + row0];
        float rs1 = scratch[row1] + scratch[64 + row1];
        float sc0 = __expf(m2[0] - nm0), sc1 = __expf(m2[1] - nm1);
        m2[0] = nm0; m2[1] = nm1;
        l2[0] = l2[0] * sc0 + rs0;
        l2[1] = l2[1] * sc1 + rs1;
#pragma unroll
        for (int nt = 0; nt < 4; nt++) {
            o[nt][0] *= sc0; o[nt][1] *= sc0;
            o[nt][2] *= sc1; o[nt][3] *= sc1;
        }

        __syncthreads();   // sum reads done -> P may overwrite KP (incl. scratch rows)
        // store P^T: [kk][q]
#pragma unroll
        for (int nt = 0; nt < 4; nt++) {
            int kkb = wn * 32 + nt * 8 + tg * 2;
            KP[kkb    ][SWZ(row0, kkb)]     = s[nt][0];
            KP[kkb + 1][SWZ(row0, kkb + 1)] = s[nt][1];
            KP[kkb    ][SWZ(row1, kkb)]     = s[nt][2];
            KP[kkb + 1][SWZ(row1, kkb + 1)] = s[nt][3];
        }
        __syncthreads();

        // ---- O += P V (tf32x3) ----
#pragma unroll
        for (int k8 = 0; k8 < 64; k8 += 8) {
            uint32_t ahi[4], alo[4];
            {
                float x0 = KP[k8 + tg][SWZ(row0, k8 + tg)];
                float x1 = KP[k8 + tg][SWZ(row1, k8 + tg)];
                float x2 = KP[k8 + tg + 4][SWZ(row0, k8 + tg + 4)];
                float x3 = KP[k8 + tg + 4][SWZ(row1, k8 + tg + 4)];
                ahi[0] = f2tf(x0); alo[0] = f2tf(x0 - __uint_as_float(ahi[0]));
                ahi[1] = f2tf(x1); alo[1] = f2tf(x1 - __uint_as_float(ahi[1]));
                ahi[2] = f2tf(x2); alo[2] = f2tf(x2 - __uint_as_float(ahi[2]));
                ahi[3] = f2tf(x3); alo[3] = f2tf(x3 - __uint_as_float(ahi[3]));
            }
#pragma unroll
            for (int nt = 0; nt < 4; nt++) {
                int n = wn * 32 + nt * 8 + g;
                float b0f = Vs[k8 + tg][SWZ(n, k8 + tg)];
                float b1f = Vs[k8 + tg + 4][SWZ(n, k8 + tg + 4)];
                uint32_t bhi[2], blo[2];
                bhi[0] = f2tf(b0f); blo[0] = f2tf(b0f - __uint_as_float(bhi[0]));
                bhi[1] = f2tf(b1f); blo[1] = f2tf(b1f - __uint_as_float(bhi[1]));
                mma_tf32(o[nt], alo, bhi);
                mma_tf32(o[nt], ahi, blo);
                mma_tf32(o[nt], ahi, bhi);
            }
        }
    }

    // write out: o / l
    float inv0 = 1.f / l2[0], inv1 = 1.f / l2[1];
    int q0 = qt * 64 + row0, q1 = qt * 64 + row1;
#pragma unroll
    for (int nt = 0; nt < 4; nt++) {
        int col = h * HD + wn * 32 + nt * 8 + tg * 2;
        *(float2*)&g_attn[(size_t)(b * SEQL + q0) * DM + col] =
            make_float2(o[nt][0] * inv0, o[nt][1] * inv0);
        *(float2*)&g_attn[(size_t)(b * SEQL + q1) * DM + col] =
            make_float2(o[nt][2] * inv1, o[nt][3] * inv1);
    }
}

// ---------------- gating: top-2 + softmax over selected logits ----------------
__global__ void __launch_bounds__(256) gate_kernel(const float* __restrict__ gW) {
    int t = blockIdx.x, tid = threadIdx.x;
    int e = tid >> 5, lane = tid & 31;
    float s = 0.f;
    for (int d = lane; d < DM; d += 32) s += g_nx2[(size_t)t * DM + d] * gW[(size_t)d * NE + e];
    for (int o = 16; o > 0; o >>= 1) s += __shfl_down_sync(0xffffffffu, s, o);
    __shared__ float lg[NE];
    if (lane == 0) lg[e] = s;
    __syncthreads();
    if (tid == 0) {
        int i0 = 0; float v0 = lg[0];
        for (int i = 1; i < NE; i++) if (lg[i] > v0) { v0 = lg[i]; i0 = i; }
        int i1 = -1; float v1 = -1e30f;
        for (int i = 0; i < NE; i++) { if (i == i0) continue; if (lg[i] > v1) { v1 = lg[i]; i1 = i; } }
        float e1 = expf(v1 - v0), sum = 1.f + e1;
        g_top_idx[t * 2] = i0; g_top_idx[t * 2 + 1] = i1;
        g_top_w[t * 2] = 1.f / sum; g_top_w[t * 2 + 1] = e1 / sum;
    }
}

// ---------------- routing (expert offsets 128-aligned) ----------------
__global__ void route_zero() {
    int i = blockIdx.x * blockDim.x + threadIdx.x;
    if (i < NE) { g_cnt[i] = 0; g_fill[i] = 0; }
    if (i < NSLOT) g_slot2tok[i] = -1;
}
__global__ void route_count() {
    int i = blockIdx.x * blockDim.x + threadIdx.x;
    if (i < NTOK * TOPK) atomicAdd(&g_cnt[g_top_idx[i]], 1);
}
__global__ void route_scan() {
    g_off[0] = 0;
    for (int e = 0; e < NE; e++)
        g_off[e + 1] = g_off[e] + ((g_cnt[e] + BM - 1) / BM) * BM;
}
__global__ void route_fill_expert() {
    int s = blockIdx.x * blockDim.x + threadIdx.x;
    if (s >= NSLOT) return;
    int e = NE - 1;
    for (int i = 0; i < NE; i++) if (s >= g_off[i] && s < g_off[i + 1]) { e = i; break; }
    g_slot_expert[s] = e;
}
__global__ void route_assign() {
    int i = blockIdx.x * blockDim.x + threadIdx.x;
    if (i >= NTOK * TOPK) return;
    int e = g_top_idx[i];
    int pos = atomicAdd(&g_fill[e], 1);
    int slot = g_off[e] + pos;
    g_slot2tok[slot] = i >> 1;
    g_tok2slot[i] = slot;
}

// ---------------- final combine ----------------
__global__ void __launch_bounds__(256) combine_kernel(float* __restrict__ out) {
    int t = blockIdx.x;
    int s0 = g_tok2slot[t * 2], s1 = g_tok2slot[t * 2 + 1];
    float w0 = g_top_w[t * 2], w1 = g_top_w[t * 2 + 1];
    for (int i = threadIdx.x; i < DM; i += blockDim.x)
        out[(size_t)t * DM + i] =
            g_x1[(size_t)t * DM + i] + w0 * g_y[(size_t)s0 * DM + i] + w1 * g_y[(size_t)s1 * DM + i];
}

// ---------------- launch: kernel launches ONLY ----------------
extern "C" void kernel_launch(void* const* d_in, const int* in_sizes, int n_in,
                              void* d_out, int out_size) {
    const float* x     = (const float*)d_in[0];
    const float* ln1_w = (const float*)d_in[1];
    const float* ln1_b = (const float*)d_in[2];
    const float* ln2_w = (const float*)d_in[3];
    const float* ln2_b = (const float*)d_in[4];
    const float* Wqkv  = (const float*)d_in[5];
    const float* bqkv  = (const float*)d_in[6];
    const float* Wo    = (const float*)d_in[7];
    const float* bo    = (const float*)d_in[8];
    const float* gateW = (const float*)d_in[9];
    const float* fc1_w = (const float*)d_in[10];
    const float* fc1_b = (const float*)d_in[11];
    const float* fc2_w = (const float*)d_in[12];
    const float* fc2_b = (const float*)d_in[13];
    float* out = (float*)d_out;

    ln1_kernel<<<NTOK, 256>>>(x, ln1_w, ln1_b);
    gemm_qkv<<<dim3(3 * DM / BN, NTOK / BM), 256>>>(Wqkv, bqkv);
    attn_mma_kernel<<<dim3(SEQL / 64, NH, BATCH), 256>>>();
    gemm_wo<<<dim3(DM / BN, NTOK / BM), 256>>>(Wo, bo, x);
    ln2_kernel<<<NTOK, 256>>>(ln2_w, ln2_b);
    gate_kernel<<<NTOK, 256>>>(gateW);
    route_zero<<<(NSLOT + 255) / 256, 256>>>();
    route_count<<<(NTOK * TOPK + 255) / 256, 256>>>();
    route_scan<<<1, 1>>>();
    route_fill_expert<<<(NSLOT + 255) / 256, 256>>>();
    route_assign<<<(NTOK * TOPK + 255) / 256, 256>>>();
    moe_fc1<<<dim3(FF / BN, NSLOT / BM), 256>>>(fc1_w, fc1_b);
    moe_fc2<<<dim3(DM / BN, NSLOT / BM), 256>>>(fc2_w, fc2_b);
    combine_kernel<<<NTOK, 256>>>(out);
    (void)in_sizes; (void)n_in; (void)out_size;
}

// round 6
// speedup vs baseline: 1.8078x; 1.8078x over previous
#include <cuda_runtime.h>
#include <cuda_bf16.h>
#include <math.h>
#include <stdint.h>

// ---- problem shape ----
#define BATCH 4
#define SEQL  1024
#define DM    1024
#define NH    16
#define HD    64
#define FF    4096
#define NE    8
#define TOPK  2
#define NTOK  (BATCH*SEQL)          // 4096 tokens
#define NSLOT 9216                  // 4096*2 + worst-case 128-align padding -> 9208 <= 9216

// GEMM tiling (tensor-core kernel)
#define BM 128
#define BN 64
#define BK 16

// ---- scratch (device globals; no runtime allocation allowed) ----
__device__ float g_nx  [(size_t)NTOK*DM];
__device__ float g_qkv [(size_t)NTOK*3*DM];
__device__ float g_attn[(size_t)NTOK*DM];
__device__ float g_x1  [(size_t)NTOK*DM];
__device__ float g_nx2 [(size_t)NTOK*DM];
__device__ int   g_top_idx[NTOK*TOPK];
__device__ float g_top_w  [NTOK*TOPK];
__device__ int   g_cnt [NE];
__device__ int   g_off [NE+1];
__device__ int   g_fill[NE];
__device__ int   g_slot2tok[NSLOT];
__device__ int   g_slot_expert[NSLOT];
__device__ int   g_tok2slot[NTOK*TOPK];
__device__ float g_h[(size_t)NSLOT*FF];
__device__ float g_y[(size_t)NSLOT*DM];

// ---------------- helpers ----------------
__device__ __forceinline__ uint32_t f2tf(float x) {
    uint32_t r;
    asm("cvt.rna.tf32.f32 %0, %1;" : "=r"(r) : "f"(x));
    return r;
}
__device__ __forceinline__ void mma_tf32(float* c, const uint32_t* a, const uint32_t* b) {
    asm volatile("mma.sync.aligned.m16n8k8.row.col.f32.tf32.tf32.f32 "
                 "{%0,%1,%2,%3}, {%4,%5,%6,%7}, {%8,%9}, {%0,%1,%2,%3};"
                 : "+f"(c[0]), "+f"(c[1]), "+f"(c[2]), "+f"(c[3])
                 : "r"(a[0]), "r"(a[1]), "r"(a[2]), "r"(a[3]), "r"(b[0]), "r"(b[1]));
}
__device__ __forceinline__ void mma_bf16(float* c, const uint32_t* a, const uint32_t* b) {
    asm volatile("mma.sync.aligned.m16n8k16.row.col.f32.bf16.bf16.f32 "
                 "{%0,%1,%2,%3}, {%4,%5,%6,%7}, {%8,%9}, {%0,%1,%2,%3};"
                 : "+f"(c[0]), "+f"(c[1]), "+f"(c[2]), "+f"(c[3])
                 : "r"(a[0]), "r"(a[1]), "r"(a[2]), "r"(a[3]), "r"(b[0]), "r"(b[1]));
}
// split x into bf16 hi (low halfword) + bf16 lo (high halfword), packed
__device__ __forceinline__ uint32_t pack_split_bf16(float x) {
    __nv_bfloat16 h = __float2bfloat16(x);
    float hf = __bfloat162float(h);
    __nv_bfloat16 l = __float2bfloat16(x - hf);
    return (uint32_t)__bfloat16_as_ushort(h) | ((uint32_t)__bfloat16_as_ushort(l) << 16);
}
__device__ __forceinline__ uint32_t prmt_b32(uint32_t a, uint32_t b, uint32_t sel) {
    uint32_t r;
    asm("prmt.b32 %0, %1, %2, %3;" : "=r"(r) : "r"(a), "r"(b), "r"(sel));
    return r;
}
#define SEL_HI 0x5410u   // [a.b0,a.b1,b.b0,b.b1] -> (hi of even k, hi of odd k)
#define SEL_LO 0x7632u   // [a.b2,a.b3,b.b2,b.b3] -> (lo of even k, lo of odd k)

// ---------------- LayerNorm ----------------
__device__ __forceinline__ void ln_body(const float* __restrict__ x, const float* __restrict__ w,
                                        const float* __restrict__ b, float* __restrict__ out) {
    int t = blockIdx.x;
    const float* row = x + (size_t)t * DM;
    float s = 0.f, s2 = 0.f;
    for (int i = threadIdx.x; i < DM; i += blockDim.x) {
        float v = row[i]; s += v; s2 += v * v;
    }
    __shared__ float sh[64];
    for (int o = 16; o > 0; o >>= 1) {
        s  += __shfl_down_sync(0xffffffffu, s,  o);
        s2 += __shfl_down_sync(0xffffffffu, s2, o);
    }
    int wid = threadIdx.x >> 5, lane = threadIdx.x & 31;
    if (lane == 0) { sh[wid] = s; sh[wid + 32] = s2; }
    __syncthreads();
    if (threadIdx.x == 0) {
        float a = 0.f, c = 0.f;
        int nw = blockDim.x >> 5;
        for (int i = 0; i < nw; i++) { a += sh[i]; c += sh[i + 32]; }
        float mu  = a / DM;
        float var = c / DM - mu * mu;
        sh[0] = mu; sh[1] = rsqrtf(var + 1e-5f);
    }
    __syncthreads();
    float mu = sh[0], rs = sh[1];
    for (int i = threadIdx.x; i < DM; i += blockDim.x)
        out[(size_t)t * DM + i] = (row[i] - mu) * rs * w[i] + b[i];
}

__global__ void __launch_bounds__(256) ln1_kernel(const float* __restrict__ x,
                                                  const float* __restrict__ w,
                                                  const float* __restrict__ b) {
    ln_body(x, w, b, g_nx);
}
__global__ void __launch_bounds__(256) ln2_kernel(const float* __restrict__ w,
                                                  const float* __restrict__ b) {
    ln_body(g_x1, w, b, g_nx2);
}

// ============ tensor-core GEMM (bf16x2 split, m16n8k16), 128x64 tile ============
template<bool GROUPED, bool ROWMAP, bool TRANSB, bool ACT, bool RESID>
__device__ __forceinline__ void mma_gemm_body(
    const float* __restrict__ A, int lda,
    const float* __restrict__ Wbase, size_t wstride,
    const float* __restrict__ biasbase, int bstride,
    const float* __restrict__ resid,
    float* __restrict__ C, int N, int K)
{
    __shared__ uint32_t As[BK][BM + 4];   // packed bf16 hi|lo ; stride 132 % 32 == 4
    __shared__ uint32_t Bs[BK][BN + 4];   // stride 68 % 32 == 4

    int m0 = blockIdx.y * BM, n0 = blockIdx.x * BN;
    const float* Bm; const float* bias;
    if (GROUPED) {
        if (m0 >= g_off[NE]) return;
        int e = g_slot_expert[m0];
        Bm   = Wbase   + (size_t)e * wstride;
        bias = biasbase + (size_t)e * bstride;
    } else {
        Bm = Wbase; bias = biasbase;
    }

    int tid  = threadIdx.x;
    int lane = tid & 31, warp = tid >> 5;
    int wm = warp & 3, wn = warp >> 2;       // 4 x 2 warp grid, warp tile 32x32
    int g  = lane >> 2, tg = lane & 3;
    int k0e = 2 * tg, k0o = 2 * tg + 1;      // even/odd k within low 8
    int k8e = k0e + 8, k8o = k0o + 8;        // within high 8

    float c[2][4][4];
#pragma unroll
    for (int mt = 0; mt < 2; mt++)
#pragma unroll
        for (int nt = 0; nt < 4; nt++)
#pragma unroll
            for (int i = 0; i < 4; i++) c[mt][nt][i] = 0.f;

    // staging indices
    int am[2], kqa[2], arow[2];
#pragma unroll
    for (int s = 0; s < 2; s++) {
        int idx = s * 256 + tid;
        am[s]  = idx >> 2;
        kqa[s] = idx & 3;
        int r = m0 + am[s];
        arow[s] = ROWMAP ? g_slot2tok[r] : r;
    }
    int kb = tid >> 4, nq = tid & 15;      // NN staging
    int nb = tid >> 2, kqb = tid & 3;      // NT staging

    float4 ra[2], rb;

    // prologue load (k0 = 0)
#pragma unroll
    for (int s = 0; s < 2; s++) {
        if (!ROWMAP || arow[s] >= 0)
            ra[s] = *(const float4*)&A[(size_t)arow[s] * lda + kqa[s] * 4];
        else
            ra[s] = make_float4(0.f, 0.f, 0.f, 0.f);
    }
    if (TRANSB) rb = *(const float4*)&Bm[(size_t)(n0 + nb) * K + kqb * 4];
    else        rb = *(const float4*)&Bm[(size_t)kb * N + n0 + nq * 4];

    for (int k0 = 0; k0 < K; k0 += BK) {
        __syncthreads();
        // commit staged regs to smem, split+packed
#pragma unroll
        for (int s = 0; s < 2; s++) {
            As[kqa[s]*4+0][am[s]] = pack_split_bf16(ra[s].x);
            As[kqa[s]*4+1][am[s]] = pack_split_bf16(ra[s].y);
            As[kqa[s]*4+2][am[s]] = pack_split_bf16(ra[s].z);
            As[kqa[s]*4+3][am[s]] = pack_split_bf16(ra[s].w);
        }
        if (TRANSB) {
            Bs[kqb*4+0][nb] = pack_split_bf16(rb.x);
            Bs[kqb*4+1][nb] = pack_split_bf16(rb.y);
            Bs[kqb*4+2][nb] = pack_split_bf16(rb.z);
            Bs[kqb*4+3][nb] = pack_split_bf16(rb.w);
        } else {
            Bs[kb][nq*4+0] = pack_split_bf16(rb.x);
            Bs[kb][nq*4+1] = pack_split_bf16(rb.y);
            Bs[kb][nq*4+2] = pack_split_bf16(rb.z);
            Bs[kb][nq*4+3] = pack_split_bf16(rb.w);
        }
        __syncthreads();

        // prefetch next K-slab
        int kn = k0 + BK;
        if (kn < K) {
#pragma unroll
            for (int s = 0; s < 2; s++) {
                if (!ROWMAP || arow[s] >= 0)
                    ra[s] = *(const float4*)&A[(size_t)arow[s] * lda + kn + kqa[s] * 4];
                else
                    ra[s] = make_float4(0.f, 0.f, 0.f, 0.f);
            }
            if (TRANSB) rb = *(const float4*)&Bm[(size_t)(n0 + nb) * K + kn + kqb * 4];
            else        rb = *(const float4*)&Bm[(size_t)(kn + kb) * N + n0 + nq * 4];
        }

        // ---- one m16n8k16 step consumes the whole BK=16 slab ----
        uint32_t ahi[2][4], alo[2][4];
#pragma unroll
        for (int mt = 0; mt < 2; mt++) {
            int mb = wm * 32 + mt * 16;
            uint32_t w00 = As[k0e][mb + g],     w01 = As[k0o][mb + g];
            uint32_t w10 = As[k0e][mb + g + 8], w11 = As[k0o][mb + g + 8];
            uint32_t w20 = As[k8e][mb + g],     w21 = As[k8o][mb + g];
            uint32_t w30 = As[k8e][mb + g + 8], w31 = As[k8o][mb + g + 8];
            ahi[mt][0] = prmt_b32(w00, w01, SEL_HI); alo[mt][0] = prmt_b32(w00, w01, SEL_LO);
            ahi[mt][1] = prmt_b32(w10, w11, SEL_HI); alo[mt][1] = prmt_b32(w10, w11, SEL_LO);
            ahi[mt][2] = prmt_b32(w20, w21, SEL_HI); alo[mt][2] = prmt_b32(w20, w21, SEL_LO);
            ahi[mt][3] = prmt_b32(w30, w31, SEL_HI); alo[mt][3] = prmt_b32(w30, w31, SEL_LO);
        }
        uint32_t bhi[4][2], blo[4][2];
#pragma unroll
        for (int nt = 0; nt < 4; nt++) {
            int n = wn * 32 + nt * 8 + g;
            uint32_t w0 = Bs[k0e][n], w1 = Bs[k0o][n];
            uint32_t w2 = Bs[k8e][n], w3 = Bs[k8o][n];
            bhi[nt][0] = prmt_b32(w0, w1, SEL_HI); blo[nt][0] = prmt_b32(w0, w1, SEL_LO);
            bhi[nt][1] = prmt_b32(w2, w3, SEL_HI); blo[nt][1] = prmt_b32(w2, w3, SEL_LO);
        }
#pragma unroll
        for (int mt = 0; mt < 2; mt++)
#pragma unroll
            for (int nt = 0; nt < 4; nt++) {
                mma_bf16(c[mt][nt], alo[mt], bhi[nt]);
                mma_bf16(c[mt][nt], ahi[mt], blo[nt]);
                mma_bf16(c[mt][nt], ahi[mt], bhi[nt]);
            }
    }

    // epilogue
#pragma unroll
    for (int mt = 0; mt < 2; mt++) {
        int r0 = m0 + wm * 32 + mt * 16 + g;
#pragma unroll
        for (int nt = 0; nt < 4; nt++) {
            int cc = n0 + wn * 32 + nt * 8 + tg * 2;
            float b0 = bias[cc], b1 = bias[cc + 1];
#pragma unroll
            for (int half = 0; half < 2; half++) {
                int r = r0 + half * 8;
                float v0 = c[mt][nt][half * 2 + 0] + b0;
                float v1 = c[mt][nt][half * 2 + 1] + b1;
                if (ACT) {
                    v0 = 0.5f * v0 * (1.0f + erff(v0 * 0.70710678118654752f));
                    v1 = 0.5f * v1 * (1.0f + erff(v1 * 0.70710678118654752f));
                }
                if (RESID) {
                    v0 += resid[(size_t)r * N + cc];
                    v1 += resid[(size_t)r * N + cc + 1];
                }
                C[(size_t)r * N + cc]     = v0;
                C[(size_t)r * N + cc + 1] = v1;
            }
        }
    }
}

__global__ void __launch_bounds__(256) gemm_qkv(const float* __restrict__ Wqkv,
                                                const float* __restrict__ bqkv) {
    mma_gemm_body<false, false, false, false, false>(g_nx, DM, Wqkv, 0, bqkv, 0, nullptr,
                                                     g_qkv, 3 * DM, DM);
}
__global__ void __launch_bounds__(256) gemm_wo(const float* __restrict__ Wo,
                                               const float* __restrict__ bo,
                                               const float* __restrict__ x) {
    mma_gemm_body<false, false, false, false, true>(g_attn, DM, Wo, 0, bo, 0, x,
                                                    g_x1, DM, DM);
}
__global__ void __launch_bounds__(256) moe_fc1(const float* __restrict__ fc1_w,
                                               const float* __restrict__ fc1_b) {
    mma_gemm_body<true, true, true, true, false>(g_nx2, DM, fc1_w, (size_t)FF * DM,
                                                 fc1_b, FF, nullptr, g_h, FF, DM);
}
__global__ void __launch_bounds__(256) moe_fc2(const float* __restrict__ fc2_w,
                                               const float* __restrict__ fc2_b) {
    mma_gemm_body<true, false, true, false, false>(g_h, FF, fc2_w, (size_t)DM * FF,
                                                   fc2_b, DM, nullptr, g_y, DM, FF);
}

// ============ tensor-core flash attention: 64q x 64kk per block, tf32x3 ============
#define SWZ(col, row) ((col) ^ (((row) & 7) << 3))

__global__ void __launch_bounds__(256) attn_mma_kernel() {
    __shared__ float Qs[64][64];   // Q^T: [d][q]
    __shared__ float KP[64][64];   // K^T: [d][kk]; later scratch + P^T: [kk][q]
    __shared__ float Vs[64][64];   // V:   [kk][d]
    float* scratch = &KP[0][0];

    const float* __restrict__ qkv = g_qkv;
    int qt = blockIdx.x, h = blockIdx.y, b = blockIdx.z;
    int tid = threadIdx.x, lane = tid & 31, warp = tid >> 5;
    int wm = warp & 3, wn = warp >> 2;
    int g = lane >> 2, tg = lane & 3;
    int row0 = wm * 16 + g, row1 = row0 + 8;

#pragma unroll
    for (int r = 0; r < 4; r++) {
        int idx = r * 256 + tid;
        int q = idx >> 4, d0 = (idx & 15) * 4;
        float4 v = *(const float4*)&qkv[((size_t)(b * SEQL + qt * 64 + q)) * (3 * DM) + h * HD + d0];
        Qs[d0 + 0][SWZ(q, d0 + 0)] = v.x;
        Qs[d0 + 1][SWZ(q, d0 + 1)] = v.y;
        Qs[d0 + 2][SWZ(q, d0 + 2)] = v.z;
        Qs[d0 + 3][SWZ(q, d0 + 3)] = v.w;
    }

    float m2[2] = {-1e30f, -1e30f}, l2[2] = {0.f, 0.f};
    float o[4][4];
#pragma unroll
    for (int nt = 0; nt < 4; nt++)
#pragma unroll
        for (int i = 0; i < 4; i++) o[nt][i] = 0.f;

    for (int kt = 0; kt <= qt; kt++) {
        __syncthreads();
#pragma unroll
        for (int r = 0; r < 4; r++) {
            int idx = r * 256 + tid;
            int kk = idx >> 4, d0 = (idx & 15) * 4;
            size_t base = ((size_t)(b * SEQL + kt * 64 + kk)) * (3 * DM) + h * HD + d0;
            float4 kv = *(const float4*)&qkv[base + DM];
            KP[d0 + 0][SWZ(kk, d0 + 0)] = kv.x;
            KP[d0 + 1][SWZ(kk, d0 + 1)] = kv.y;
            KP[d0 + 2][SWZ(kk, d0 + 2)] = kv.z;
            KP[d0 + 3][SWZ(kk, d0 + 3)] = kv.w;
            float4 vv = *(const float4*)&qkv[base + 2 * DM];
            *(float4*)&Vs[kk][SWZ(d0, kk)] = vv;
        }
        __syncthreads();

        // ---- S = Q K^T (tf32x3) ----
        float s[4][4];
#pragma unroll
        for (int nt = 0; nt < 4; nt++)
#pragma unroll
            for (int i = 0; i < 4; i++) s[nt][i] = 0.f;
#pragma unroll
        for (int k8 = 0; k8 < 64; k8 += 8) {
            uint32_t ahi[4], alo[4];
            {
                float x0 = Qs[k8 + tg][SWZ(row0, k8 + tg)];
                float x1 = Qs[k8 + tg][SWZ(row1, k8 + tg)];
                float x2 = Qs[k8 + tg + 4][SWZ(row0, k8 + tg + 4)];
                float x3 = Qs[k8 + tg + 4][SWZ(row1, k8 + tg + 4)];
                ahi[0] = f2tf(x0); alo[0] = f2tf(x0 - __uint_as_float(ahi[0]));
                ahi[1] = f2tf(x1); alo[1] = f2tf(x1 - __uint_as_float(ahi[1]));
                ahi[2] = f2tf(x2); alo[2] = f2tf(x2 - __uint_as_float(ahi[2]));
                ahi[3] = f2tf(x3); alo[3] = f2tf(x3 - __uint_as_float(ahi[3]));
            }
#pragma unroll
            for (int nt = 0; nt < 4; nt++) {
                int n = wn * 32 + nt * 8 + g;
                float b0f = KP[k8 + tg][SWZ(n, k8 + tg)];
                float b1f = KP[k8 + tg + 4][SWZ(n, k8 + tg + 4)];
                uint32_t bhi[2], blo[2];
                bhi[0] = f2tf(b0f); blo[0] = f2tf(b0f - __uint_as_float(bhi[0]));
                bhi[1] = f2tf(b1f); blo[1] = f2tf(b1f - __uint_as_float(bhi[1]));
                mma_tf32(s[nt], alo, bhi);
                mma_tf32(s[nt], ahi, blo);
                mma_tf32(s[nt], ahi, bhi);
            }
        }

        bool diag = (kt == qt);
#pragma unroll
        for (int nt = 0; nt < 4; nt++) {
            int col = wn * 32 + nt * 8 + tg * 2;
#pragma unroll
            for (int i = 0; i < 4; i++) {
                float sv = s[nt][i] * 0.125f;
                int cc = col + (i & 1);
                int rr = (i < 2) ? row0 : row1;
                if (diag && cc > rr) sv = -1e30f;
                s[nt][i] = sv;
            }
        }
        float pm0 = -1e30f, pm1 = -1e30f;
#pragma unroll
        for (int nt = 0; nt < 4; nt++) {
            pm0 = fmaxf(pm0, fmaxf(s[nt][0], s[nt][1]));
            pm1 = fmaxf(pm1, fmaxf(s[nt][2], s[nt][3]));
        }
        pm0 = fmaxf(pm0, __shfl_xor_sync(0xffffffffu, pm0, 1));
        pm0 = fmaxf(pm0, __shfl_xor_sync(0xffffffffu, pm0, 2));
        pm1 = fmaxf(pm1, __shfl_xor_sync(0xffffffffu, pm1, 1));
        pm1 = fmaxf(pm1, __shfl_xor_sync(0xffffffffu, pm1, 2));

        __syncthreads();
        scratch[wn * 64 + row0] = pm0;
        scratch[wn * 64 + row1] = pm1;
        __syncthreads();
        float nm0 = fmaxf(m2[0], fmaxf(scratch[row0], scratch[64 + row0]));
        float nm1 = fmaxf(m2[1], fmaxf(scratch[row1], scratch[64 + row1]));

        float ps0 = 0.f, ps1 = 0.f;
#pragma unroll
        for (int nt = 0; nt < 4; nt++) {
            s[nt][0] = __expf(s[nt][0] - nm0); ps0 += s[nt][0];
            s[nt][1] = __expf(s[nt][1] - nm0); ps0 += s[nt][1];
            s[nt][2] = __expf(s[nt][2] - nm1); ps1 += s[nt][2];
            s[nt][3] = __expf(s[nt][3] - nm1); ps1 += s[nt][3];
        }
        ps0 += __shfl_xor_sync(0xffffffffu, ps0, 1);
        ps0 += __shfl_xor_sync(0xffffffffu, ps0, 2);
        ps1 += __shfl_xor_sync(0xffffffffu, ps1, 1);
        ps1 += __shfl_xor_sync(0xffffffffu, ps1, 2);

        __syncthreads();
        scratch[wn * 64 + row0] = ps0;
        scratch[wn * 64 + row1] = ps1;
        __syncthreads();
        float rs0 = scratch[row0] + scratch[64 + row0];
        float rs1 = scratch[row1] + scratch[64 + row1];
        float sc0 = __expf(m2[0] - nm0), sc1 = __expf(m2[1] - nm1);
        m2[0] = nm0; m2[1] = nm1;
        l2[0] = l2[0] * sc0 + rs0;
        l2[1] = l2[1] * sc1 + rs1;
#pragma unroll
        for (int nt = 0; nt < 4; nt++) {
            o[nt][0] *= sc0; o[nt][1] *= sc0;
            o[nt][2] *= sc1; o[nt][3] *= sc1;
        }

        __syncthreads();
#pragma unroll
        for (int nt = 0; nt < 4; nt++) {
            int kkb = wn * 32 + nt * 8 + tg * 2;
            KP[kkb    ][SWZ(row0, kkb)]     = s[nt][0];
            KP[kkb + 1][SWZ(row0, kkb + 1)] = s[nt][1];
            KP[kkb    ][SWZ(row1, kkb)]     = s[nt][2];
            KP[kkb + 1][SWZ(row1, kkb + 1)] = s[nt][3];
        }
        __syncthreads();

        // ---- O += P V (tf32x3) ----
#pragma unroll
        for (int k8 = 0; k8 < 64; k8 += 8) {
            uint32_t ahi[4], alo[4];
            {
                float x0 = KP[k8 + tg][SWZ(row0, k8 + tg)];
                float x1 = KP[k8 + tg][SWZ(row1, k8 + tg)];
                float x2 = KP[k8 + tg + 4][SWZ(row0, k8 + tg + 4)];
                float x3 = KP[k8 + tg + 4][SWZ(row1, k8 + tg + 4)];
                ahi[0] = f2tf(x0); alo[0] = f2tf(x0 - __uint_as_float(ahi[0]));
                ahi[1] = f2tf(x1); alo[1] = f2tf(x1 - __uint_as_float(ahi[1]));
                ahi[2] = f2tf(x2); alo[2] = f2tf(x2 - __uint_as_float(ahi[2]));
                ahi[3] = f2tf(x3); alo[3] = f2tf(x3 - __uint_as_float(ahi[3]));
            }
#pragma unroll
            for (int nt = 0; nt < 4; nt++) {
                int n = wn * 32 + nt * 8 + g;
                float b0f = Vs[k8 + tg][SWZ(n, k8 + tg)];
                float b1f = Vs[k8 + tg + 4][SWZ(n, k8 + tg + 4)];
                uint32_t bhi[2], blo[2];
                bhi[0] = f2tf(b0f); blo[0] = f2tf(b0f - __uint_as_float(bhi[0]));
                bhi[1] = f2tf(b1f); blo[1] = f2tf(b1f - __uint_as_float(bhi[1]));
                mma_tf32(o[nt], alo, bhi);
                mma_tf32(o[nt], ahi, blo);
                mma_tf32(o[nt], ahi, bhi);
            }
        }
    }

    float inv0 = 1.f / l2[0], inv1 = 1.f / l2[1];
    int q0 = qt * 64 + row0, q1 = qt * 64 + row1;
#pragma unroll
    for (int nt = 0; nt < 4; nt++) {
        int col = h * HD + wn * 32 + nt * 8 + tg * 2;
        *(float2*)&g_attn[(size_t)(b * SEQL + q0) * DM + col] =
            make_float2(o[nt][0] * inv0, o[nt][1] * inv0);
        *(float2*)&g_attn[(size_t)(b * SEQL + q1) * DM + col] =
            make_float2(o[nt][2] * inv1, o[nt][3] * inv1);
    }
}

// ---------------- gating: top-2 + softmax over selected logits ----------------
__global__ void __launch_bounds__(256) gate_kernel(const float* __restrict__ gW) {
    int t = blockIdx.x, tid = threadIdx.x;
    int e = tid >> 5, lane = tid & 31;
    float s = 0.f;
    for (int d = lane; d < DM; d += 32) s += g_nx2[(size_t)t * DM + d] * gW[(size_t)d * NE + e];
    for (int o = 16; o > 0; o >>= 1) s += __shfl_down_sync(0xffffffffu, s, o);
    __shared__ float lg[NE];
    if (lane == 0) lg[e] = s;
    __syncthreads();
    if (tid == 0) {
        int i0 = 0; float v0 = lg[0];
        for (int i = 1; i < NE; i++) if (lg[i] > v0) { v0 = lg[i]; i0 = i; }
        int i1 = -1; float v1 = -1e30f;
        for (int i = 0; i < NE; i++) { if (i == i0) continue; if (lg[i] > v1) { v1 = lg[i]; i1 = i; } }
        float e1 = expf(v1 - v0), sum = 1.f + e1;
        g_top_idx[t * 2] = i0; g_top_idx[t * 2 + 1] = i1;
        g_top_w[t * 2] = 1.f / sum; g_top_w[t * 2 + 1] = e1 / sum;
    }
}

// ---------------- routing (expert offsets 128-aligned) ----------------
__global__ void route_zero() {
    int i = blockIdx.x * blockDim.x + threadIdx.x;
    if (i < NE) { g_cnt[i] = 0; g_fill[i] = 0; }
    if (i < NSLOT) g_slot2tok[i] = -1;
}
__global__ void route_count() {
    int i = blockIdx.x * blockDim.x + threadIdx.x;
    if (i < NTOK * TOPK) atomicAdd(&g_cnt[g_top_idx[i]], 1);
}
__global__ void route_scan() {
    g_off[0] = 0;
    for (int e = 0; e < NE; e++)
        g_off[e + 1] = g_off[e] + ((g_cnt[e] + BM - 1) / BM) * BM;
}
__global__ void route_fill_expert() {
    int s = blockIdx.x * blockDim.x + threadIdx.x;
    if (s >= NSLOT) return;
    int e = NE - 1;
    for (int i = 0; i < NE; i++) if (s >= g_off[i] && s < g_off[i + 1]) { e = i; break; }
    g_slot_expert[s] = e;
}
__global__ void route_assign() {
    int i = blockIdx.x * blockDim.x + threadIdx.x;
    if (i >= NTOK * TOPK) return;
    int e = g_top_idx[i];
    int pos = atomicAdd(&g_fill[e], 1);
    int slot = g_off[e] + pos;
    g_slot2tok[slot] = i >> 1;
    g_tok2slot[i] = slot;
}

// ---------------- final combine ----------------
__global__ void __launch_bounds__(256) combine_kernel(float* __restrict__ out) {
    int t = blockIdx.x;
    int s0 = g_tok2slot[t * 2], s1 = g_tok2slot[t * 2 + 1];
    float w0 = g_top_w[t * 2], w1 = g_top_w[t * 2 + 1];
    for (int i = threadIdx.x; i < DM; i += blockDim.x)
        out[(size_t)t * DM + i] =
            g_x1[(size_t)t * DM + i] + w0 * g_y[(size_t)s0 * DM + i] + w1 * g_y[(size_t)s1 * DM + i];
}

// ---------------- launch: kernel launches ONLY ----------------
extern "C" void kernel_launch(void* const* d_in, const int* in_sizes, int n_in,
                              void* d_out, int out_size) {
    const float* x     = (const float*)d_in[0];
    const float* ln1_w = (const float*)d_in[1];
    const float* ln1_b = (const float*)d_in[2];
    const float* ln2_w = (const float*)d_in[3];
    const float* ln2_b = (const float*)d_in[4];
    const float* Wqkv  = (const float*)d_in[5];
    const float* bqkv  = (const float*)d_in[6];
    const float* Wo    = (const float*)d_in[7];
    const float* bo    = (const float*)d_in[8];
    const float* gateW = (const float*)d_in[9];
    const float* fc1_w = (const float*)d_in[10];
    const float* fc1_b = (const float*)d_in[11];
    const float* fc2_w = (const float*)d_in[12];
    const float* fc2_b = (const float*)d_in[13];
    float* out = (float*)d_out;

    ln1_kernel<<<NTOK, 256>>>(x, ln1_w, ln1_b);
    gemm_qkv<<<dim3(3 * DM / BN, NTOK / BM), 256>>>(Wqkv, bqkv);
    attn_mma_kernel<<<dim3(SEQL / 64, NH, BATCH), 256>>>();
    gemm_wo<<<dim3(DM / BN, NTOK / BM), 256>>>(Wo, bo, x);
    ln2_kernel<<<NTOK, 256>>>(ln2_w, ln2_b);
    gate_kernel<<<NTOK, 256>>>(gateW);
    route_zero<<<(NSLOT + 255) / 256, 256>>>();
    route_count<<<(NTOK * TOPK + 255) / 256, 256>>>();
    route_scan<<<1, 1>>>();
    route_fill_expert<<<(NSLOT + 255) / 256, 256>>>();
    route_assign<<<(NTOK * TOPK + 255) / 256, 256>>>();
    moe_fc1<<<dim3(FF / BN, NSLOT / BM), 256>>>(fc1_w, fc1_b);
    moe_fc2<<<dim3(DM / BN, NSLOT / BM), 256>>>(fc2_w, fc2_b);
    combine_kernel<<<NTOK, 256>>>(out);
    (void)in_sizes; (void)n_in; (void)out_size;
}